// round 3
// baseline (speedup 1.0000x reference)
#include <cuda_runtime.h>

// RoPE_90847148245015 — block-sparse RoPE rotation, pure streaming kernel.
// feats: [B=16, C=256, H=128, W=128] fp32   (d_in[0])
// R:     [H=128, C=256, C=256] fp32          (d_in[1])
// out:   [B=16, C=256, H=128, W=128] fp32
//
// out[b,2k,  h,w] = R[h,2k,2k]    *f[b,2k,h,w] + R[h,2k,2k+1]*f[b,2k+1,h,w]
// out[b,2k+1,h,w] = R[h,2k+1,2k+1]*f[b,2k+1,h,w] + R[h,2k+1,2k]*f[b,2k,h,w]
//
// R3: unroll x4 over batch (b3, b3+4, b3+8, b3+12) -> 8 independent
// front-batched LDG.128 per thread, same 4 warp-uniform R loads.
// Streaming hints (__ldcs/__stcs) kept from R2.

__global__ __launch_bounds__(256) void rope_rot_kernel(
    const float* __restrict__ feats,
    const float* __restrict__ R,
    float* __restrict__ out)
{
    const int idx = blockIdx.x * 256 + threadIdx.x;
    // idx layout: [b2:2][k:7][h:7][w4:5]  (b in {b2, b2+4, b2+8, b2+12})
    const int w4 = idx & 31;
    const int h  = (idx >> 5) & 127;
    const int k  = (idx >> 12) & 127;
    const int b2 = idx >> 19;          // 0..3

    // R[h, 2k, 2k] ; element stride: h*65536 + row*256 + col
    const int rbase = (h << 16) + (k << 9) + (k << 1);
    const float ce = __ldg(R + rbase);        // cos  (even row)
    const float se = __ldg(R + rbase + 1);    // -sin
    const float so = __ldg(R + rbase + 256);  // +sin
    const float co = __ldg(R + rbase + 257);  // cos  (odd row)

    // float4 indexing: plane stride 4096, row stride 32, batch stride 256*4096
    const int base = (((b2 << 8) + (k << 1)) << 12) + (h << 5) + w4;
    const int BSTR = 4 << 20;                 // 4 batches * 256*4096 float4s

    const float4* __restrict__ f4 = reinterpret_cast<const float4*>(feats);
    float4* __restrict__ o4 = reinterpret_cast<float4*>(out);

    // 8 independent streaming loads, front-batched for MLP
    float4 fe[4], fo[4];
#pragma unroll
    for (int u = 0; u < 4; u++) {
        fe[u] = __ldcs(f4 + base + u * BSTR);
        fo[u] = __ldcs(f4 + base + u * BSTR + 4096);
    }

#pragma unroll
    for (int u = 0; u < 4; u++) {
        float4 oe, oo;
        oe.x = fmaf(ce, fe[u].x, se * fo[u].x);
        oe.y = fmaf(ce, fe[u].y, se * fo[u].y);
        oe.z = fmaf(ce, fe[u].z, se * fo[u].z);
        oe.w = fmaf(ce, fe[u].w, se * fo[u].w);
        oo.x = fmaf(co, fo[u].x, so * fe[u].x);
        oo.y = fmaf(co, fo[u].y, so * fe[u].y);
        oo.z = fmaf(co, fo[u].z, so * fe[u].z);
        oo.w = fmaf(co, fo[u].w, so * fe[u].w);
        __stcs(o4 + base + u * BSTR,        oe);
        __stcs(o4 + base + u * BSTR + 4096, oo);
    }
}

extern "C" void kernel_launch(void* const* d_in, const int* in_sizes, int n_in,
                              void* d_out, int out_size) {
    const float* feats = (const float*)d_in[0];
    const float* R     = (const float*)d_in[1];
    float* out         = (float*)d_out;

    // threads: (B/4)*K*H*(W/4) = 4*128*128*32 = 2,097,152
    const int total = 4 * 128 * 128 * 32;
    rope_rot_kernel<<<total / 256, 256>>>(feats, R, out);
}